// round 14
// baseline (speedup 1.0000x reference)
#include <cuda_runtime.h>
#include <cstdint>
#include <math.h>

// Problem constants
static constexpr int B  = 8;
static constexpr int S  = 1024;
static constexpr int D  = 1024;
static constexpr int H  = 16;
static constexpr int DK = 64;
static constexpr int M  = B * S;

static constexpr size_t YSIZE    = (size_t)B * S * D;
static constexpr size_t ATTNSIZE = (size_t)B * H * S * S;

// Scratch
__device__ float g_Q[YSIZE];
__device__ float g_K[YSIZE];
__device__ float g_V[YSIZE];
__device__ float g_ctx[YSIZE];
__device__ float g_x[YSIZE];
__device__ float g_attn[ATTNSIZE];
__device__ float g_linv[(size_t)B * H * S];   // per-row 1/l

__device__ __forceinline__ uint32_t f32_to_tf32_rn(float x) {
    uint32_t r;
    asm("cvt.rna.tf32.f32 %0, %1;" : "=r"(r) : "f"(x));
    return r;
}

__device__ __forceinline__ float ex2f(float x) {
    float r;
    asm("ex2.approx.f32 %0, %1;" : "=f"(r) : "f"(x));
    return r;
}

__device__ __forceinline__ void mma_tf32(float c[4], const uint32_t a[4], const uint32_t b[2]) {
    asm volatile(
        "mma.sync.aligned.m16n8k8.row.col.f32.tf32.tf32.f32 "
        "{%0,%1,%2,%3}, {%4,%5,%6,%7}, {%8,%9}, {%0,%1,%2,%3};"
        : "+f"(c[0]), "+f"(c[1]), "+f"(c[2]), "+f"(c[3])
        : "r"(a[0]), "r"(a[1]), "r"(a[2]), "r"(a[3]), "r"(b[0]), "r"(b[1]));
}

// ===========================================================================
// Dense GEMM body (unchanged): tf32 warp MMA, warp tile 64x64, 4 warps,
// 2-stage double-buffered smem, register prefetch.
// ===========================================================================
static constexpr int BKg = 16;

__device__ __forceinline__ void gemm_body(
    const float* __restrict__ A, const float* __restrict__ W,
    const float* __restrict__ bias, const float* __restrict__ res,
    float* __restrict__ C, int Kk, int Nn, int bm, int bn)
{
    __shared__ uint32_t As[2][128][20];
    __shared__ uint32_t Ws[2][128][20];

    const int tid  = threadIdx.x;        // 0..127
    const int wid  = tid >> 5;           // 0..3
    const int lane = tid & 31;
    const int warp_m = wid >> 1;
    const int warp_n = wid & 1;
    const int gID = lane >> 2;
    const int tig = lane & 3;

    const int srow = tid >> 2;           // 0..31
    const int skc  = (tid & 3) * 4;

    const float* Ag[4];
    const float* Wg[4];
#pragma unroll
    for (int i = 0; i < 4; i++) {
        Ag[i] = A + (size_t)(bm + srow + i * 32) * Kk + skc;
        Wg[i] = W + (size_t)(bn + srow + i * 32) * Kk + skc;
    }

    float acc[4][8][4];
#pragma unroll
    for (int i = 0; i < 4; i++)
#pragma unroll
        for (int j = 0; j < 8; j++)
#pragma unroll
            for (int r = 0; r < 4; r++) acc[i][j][r] = 0.f;

    const int NCH = Kk / BKg;

    float4 ra[4], rw[4];
#pragma unroll
    for (int i = 0; i < 4; i++) {
        ra[i] = *(const float4*)Ag[i];
        rw[i] = *(const float4*)Wg[i];
    }

#pragma unroll
    for (int i = 0; i < 4; i++) {
        *(uint4*)&As[0][srow + i * 32][skc] = make_uint4(
            f32_to_tf32_rn(ra[i].x), f32_to_tf32_rn(ra[i].y),
            f32_to_tf32_rn(ra[i].z), f32_to_tf32_rn(ra[i].w));
        *(uint4*)&Ws[0][srow + i * 32][skc] = make_uint4(
            f32_to_tf32_rn(rw[i].x), f32_to_tf32_rn(rw[i].y),
            f32_to_tf32_rn(rw[i].z), f32_to_tf32_rn(rw[i].w));
    }
    __syncthreads();

    for (int c = 0; c < NCH; c++) {
        const int s = c & 1;
        const bool more = (c + 1 < NCH);

        if (more) {
#pragma unroll
            for (int i = 0; i < 4; i++) {
                Ag[i] += BKg; Wg[i] += BKg;
                ra[i] = *(const float4*)Ag[i];
                rw[i] = *(const float4*)Wg[i];
            }
        }

#pragma unroll
        for (int kk = 0; kk < BKg; kk += 8) {
            uint32_t af[4][4];
            uint32_t bf[8][2];
#pragma unroll
            for (int mi = 0; mi < 4; mi++) {
                const int mr = warp_m * 64 + mi * 16 + gID;
                af[mi][0] = As[s][mr][kk + tig];
                af[mi][1] = As[s][mr + 8][kk + tig];
                af[mi][2] = As[s][mr][kk + tig + 4];
                af[mi][3] = As[s][mr + 8][kk + tig + 4];
            }
#pragma unroll
            for (int nj = 0; nj < 8; nj++) {
                const int nr = warp_n * 64 + nj * 8 + gID;
                bf[nj][0] = Ws[s][nr][kk + tig];
                bf[nj][1] = Ws[s][nr][kk + tig + 4];
            }
#pragma unroll
            for (int mi = 0; mi < 4; mi++)
#pragma unroll
                for (int nj = 0; nj < 8; nj++)
                    mma_tf32(acc[mi][nj], af[mi], bf[nj]);
        }

        if (more) {
            const int t = s ^ 1;
#pragma unroll
            for (int i = 0; i < 4; i++) {
                *(uint4*)&As[t][srow + i * 32][skc] = make_uint4(
                    f32_to_tf32_rn(ra[i].x), f32_to_tf32_rn(ra[i].y),
                    f32_to_tf32_rn(ra[i].z), f32_to_tf32_rn(ra[i].w));
                *(uint4*)&Ws[t][srow + i * 32][skc] = make_uint4(
                    f32_to_tf32_rn(rw[i].x), f32_to_tf32_rn(rw[i].y),
                    f32_to_tf32_rn(rw[i].z), f32_to_tf32_rn(rw[i].w));
            }
        }
        __syncthreads();
    }

    const bool has_res = (res != nullptr);
#pragma unroll
    for (int mi = 0; mi < 4; mi++) {
        const int r0 = bm + warp_m * 64 + mi * 16 + gID;
#pragma unroll
        for (int nj = 0; nj < 8; nj++) {
            const int c0 = bn + warp_n * 64 + nj * 8 + tig * 2;
            const float b0 = bias[c0], b1 = bias[c0 + 1];
            float2 o0 = make_float2(acc[mi][nj][0] + b0, acc[mi][nj][1] + b1);
            float2 o1 = make_float2(acc[mi][nj][2] + b0, acc[mi][nj][3] + b1);
            const size_t i0 = (size_t)r0 * Nn + c0;
            const size_t i1 = (size_t)(r0 + 8) * Nn + c0;
            if (has_res) {
                float2 rv0 = *(const float2*)&res[i0];
                float2 rv1 = *(const float2*)&res[i1];
                o0.x += rv0.x; o0.y += rv0.y;
                o1.x += rv1.x; o1.y += rv1.y;
            }
            *(float2*)&C[i0] = o0;
            *(float2*)&C[i1] = o1;
        }
    }
}

// Merged QKV projection + attn upper-triangle zero-fill (overlapped).
__global__ void __launch_bounds__(128, 2) qkv_gemm(
    const float* __restrict__ q_in, const float* __restrict__ k_in,
    const float* __restrict__ v_in,
    const float* __restrict__ wq, const float* __restrict__ wk,
    const float* __restrict__ wv,
    const float* __restrict__ bq, const float* __restrict__ bk,
    const float* __restrict__ bv,
    float* __restrict__ Qo, float* __restrict__ Ko, float* __restrict__ Vo,
    float* __restrict__ attnout)
{
    if (blockIdx.z == 3) {
        // 3584 zero tiles (128x128) = 512 blocks * 7 tiles
        const int bid = blockIdx.y * 8 + blockIdx.x;          // 0..511
        for (int t = bid * 7; t < bid * 7 + 7; t++) {
            const int bh = t / 28;
            int r = t % 28;
            int qt = 0;
            while (r >= 7 - qt) { r -= 7 - qt; qt++; }
            const int kt = qt + 1 + r;
            float* tile = attnout + (size_t)bh * S * S
                        + (size_t)qt * 128 * S + (size_t)kt * 128;
            const float4 z4 = make_float4(0.f, 0.f, 0.f, 0.f);
            for (int i = threadIdx.x; i < 128 * 32; i += 128) {
                const int row = i >> 5, c4 = i & 31;
                *(float4*)&tile[(size_t)row * S + c4 * 4] = z4;
            }
        }
        return;
    }
    const float* A; const float* W; const float* bias; float* C;
    if (blockIdx.z == 0)      { A = q_in; W = wq; bias = bq; C = Qo; }
    else if (blockIdx.z == 1) { A = k_in; W = wk; bias = bk; C = Ko; }
    else                      { A = v_in; W = wv; bias = bv; C = Vo; }
    gemm_body(A, W, bias, nullptr, C, D, D, blockIdx.y * 128, blockIdx.x * 128);
}

// Output projection (z=0) + attn row-normalization (z=1), overlapped.
__global__ void __launch_bounds__(128, 2) outproj_gemm(
    const float* __restrict__ A, const float* __restrict__ W,
    const float* __restrict__ bias, const float* __restrict__ res,
    float* __restrict__ C,
    float* __restrict__ attnout, const float* __restrict__ linv)
{
    if (blockIdx.z == 1) {
        // 1024 strips (bh, qt); block t handles strips t and 1023-t
        // (loads balance: (qt+1) + (8-qt) = 9 tiles each).
        const int t = blockIdx.y * 8 + blockIdx.x;            // 0..511
        const int strips[2] = { t, 1023 - t };
#pragma unroll
        for (int si = 0; si < 2; si++) {
            const int s  = strips[si];
            const int bh = s >> 3;
            const int qt = s & 7;
            const int q0 = qt * 128;
            float* arow = attnout + (size_t)bh * S * S;
            const float* lrow = linv + (size_t)bh * S;
            const int nf4 = (qt + 1) * 32;                    // float4s per row
            for (int row = 0; row < 128; row++) {
                const float iv = lrow[q0 + row];
                float4* p = (float4*)&arow[(size_t)(q0 + row) * S];
                for (int c = threadIdx.x; c < nf4; c += 128) {
                    float4 v = p[c];
                    v.x *= iv; v.y *= iv; v.z *= iv; v.w *= iv;
                    p[c] = v;
                }
            }
        }
        return;
    }
    gemm_body(A, W, bias, res, C, D, D, blockIdx.y * 128, blockIdx.x * 128);
}

// ===========================================================================
// Fused attention, SINGLE pass: S computed once; unnormalized p -> attn gmem
// + Ps smem; l accumulated per-thread; ctx = O_unnorm * (1/l); 1/l saved.
// ===========================================================================
static constexpr int FB_QP = 68;
static constexpr int FB_KP = 68;
static constexpr int FB_VP = 72;
static constexpr int FB_PP = 68;
static constexpr int FB_OFF_K = 128 * FB_QP;
static constexpr int FB_OFF_V = FB_OFF_K + 64 * FB_KP;
static constexpr int FB_OFF_P = FB_OFF_V + 64 * FB_VP;
static constexpr int FB_SMEM  = (FB_OFF_P + 128 * FB_PP) * 4;   // 105472

__global__ void __launch_bounds__(256, 2) fused_attn(
    const float* __restrict__ Qg, const float* __restrict__ Kg,
    const float* __restrict__ Vg, float* __restrict__ attn,
    float* __restrict__ ctx, float* __restrict__ linv)
{
    extern __shared__ uint32_t sm[];
    uint32_t (*Qs)[FB_QP] = (uint32_t(*)[FB_QP])sm;
    uint32_t (*Ks)[FB_KP] = (uint32_t(*)[FB_KP])(sm + FB_OFF_K);
    uint32_t (*Vs)[FB_VP] = (uint32_t(*)[FB_VP])(sm + FB_OFF_V);
    uint32_t (*Ps)[FB_PP] = (uint32_t(*)[FB_PP])(sm + FB_OFF_P);

    const int NQT = S / 128;
    const int qt = NQT - 1 - blockIdx.x;
    const int bh = blockIdx.y;
    const int b = bh >> 4, h = bh & 15;
    const int q0 = qt * 128;

    const float* Qbase = Qg + (size_t)b * S * D + h * DK;
    const float* Kbase = Kg + (size_t)b * S * D + h * DK;
    const float* Vbase = Vg + (size_t)b * S * D + h * DK;
    float* arow = attn + (size_t)bh * S * S;

    const int tid  = threadIdx.x;
    const int wid  = tid >> 5;
    const int lane = tid & 31;
    const int gID  = lane >> 2;
    const int tig  = lane & 3;
    const int w16  = wid * 16;
    const int r0l  = w16 + gID;
    const int r1l  = r0l + 8;
    const int q0g  = q0 + r0l;
    const int q1g  = q0 + r1l;

    const int str = tid >> 4;
    const int stc = (tid & 15) * 4;

    // Stage Q strip (128 x 64)
#pragma unroll
    for (int i = 0; i < 8; i++) {
        const int f = tid + i * 256;
        const int r = f >> 4, c4 = f & 15;
        float4 v = *(const float4*)&Qbase[(size_t)(q0 + r) * D + c4 * 4];
        *(uint4*)&Qs[r][c4 * 4] = make_uint4(
            f32_to_tf32_rn(v.x), f32_to_tf32_rn(v.y),
            f32_to_tf32_rn(v.z), f32_to_tf32_rn(v.w));
    }

    const float C2 = 0.18033688011112042f;   // 0.125 * log2(e)
    const int NKT = (qt + 1) * 2;
    float l0 = 0.f, l1 = 0.f;

    float oacc[8][4];
#pragma unroll
    for (int j = 0; j < 8; j++)
#pragma unroll
        for (int r = 0; r < 4; r++) oacc[j][r] = 0.f;

    float4 pk[4], pv[4];
#pragma unroll
    for (int i = 0; i < 4; i++) {
        pk[i] = *(const float4*)&Kbase[(size_t)(str + i * 16) * D + stc];
        pv[i] = *(const float4*)&Vbase[(size_t)(str + i * 16) * D + stc];
    }

    for (int kt = 0; kt < NKT; kt++) {
        const int k0 = kt * 64;
        const bool tail = (k0 + 63 > q0);

        if (kt > 0) __syncthreads();
#pragma unroll
        for (int i = 0; i < 4; i++) {
            *(uint4*)&Ks[str + i * 16][stc] = make_uint4(
                f32_to_tf32_rn(pk[i].x), f32_to_tf32_rn(pk[i].y),
                f32_to_tf32_rn(pk[i].z), f32_to_tf32_rn(pk[i].w));
            *(uint4*)&Vs[str + i * 16][stc] = make_uint4(
                f32_to_tf32_rn(pv[i].x), f32_to_tf32_rn(pv[i].y),
                f32_to_tf32_rn(pv[i].z), f32_to_tf32_rn(pv[i].w));
        }
        __syncthreads();

        if (kt + 1 < NKT) {
            const int kn = k0 + 64;
#pragma unroll
            for (int i = 0; i < 4; i++) {
                pk[i] = *(const float4*)&Kbase[(size_t)(kn + str + i * 16) * D + stc];
                pv[i] = *(const float4*)&Vbase[(size_t)(kn + str + i * 16) * D + stc];
            }
        }

        float sacc[8][4];
#pragma unroll
        for (int j = 0; j < 8; j++)
#pragma unroll
            for (int r = 0; r < 4; r++) sacc[j][r] = 0.f;

#pragma unroll
        for (int kk = 0; kk < 64; kk += 8) {
            uint32_t af[4];
            af[0] = Qs[r0l][kk + tig];
            af[1] = Qs[r1l][kk + tig];
            af[2] = Qs[r0l][kk + tig + 4];
            af[3] = Qs[r1l][kk + tig + 4];
#pragma unroll
            for (int nj = 0; nj < 8; nj++) {
                uint32_t bf[2];
                const int nr = nj * 8 + gID;
                bf[0] = Ks[nr][kk + tig];
                bf[1] = Ks[nr][kk + tig + 4];
                mma_tf32(sacc[nj], af, bf);
            }
        }

        // p_unnorm = ex2(s*C2); write attn (unnormalized); stage Ps; accum l
#pragma unroll
        for (int nj = 0; nj < 8; nj++) {
            const int c0 = k0 + nj * 8 + 2 * tig, c1 = c0 + 1;
            float p00, p01, p10, p11;
            if (tail) {
                p00 = (c0 <= q0g) ? ex2f(sacc[nj][0] * C2) : 0.f;
                p01 = (c1 <= q0g) ? ex2f(sacc[nj][1] * C2) : 0.f;
                p10 = (c0 <= q1g) ? ex2f(sacc[nj][2] * C2) : 0.f;
                p11 = (c1 <= q1g) ? ex2f(sacc[nj][3] * C2) : 0.f;
            } else {
                p00 = ex2f(sacc[nj][0] * C2);
                p01 = ex2f(sacc[nj][1] * C2);
                p10 = ex2f(sacc[nj][2] * C2);
                p11 = ex2f(sacc[nj][3] * C2);
            }
            l0 += p00 + p01;
            l1 += p10 + p11;
            *(float2*)&arow[(size_t)q0g * S + c0] = make_float2(p00, p01);
            *(float2*)&arow[(size_t)q1g * S + c0] = make_float2(p10, p11);
            *(uint2*)&Ps[r0l][nj * 8 + 2 * tig] =
                make_uint2(f32_to_tf32_rn(p00), f32_to_tf32_rn(p01));
            *(uint2*)&Ps[r1l][nj * 8 + 2 * tig] =
                make_uint2(f32_to_tf32_rn(p10), f32_to_tf32_rn(p11));
        }
        __syncwarp();   // Ps rows are per-warp

        // O_unnorm += P_unnorm(16x64 per warp) @ V(64x64)
#pragma unroll
        for (int kk = 0; kk < 64; kk += 8) {
            uint32_t af[4];
            af[0] = Ps[r0l][kk + tig];
            af[1] = Ps[r1l][kk + tig];
            af[2] = Ps[r0l][kk + tig + 4];
            af[3] = Ps[r1l][kk + tig + 4];
#pragma unroll
            for (int nj = 0; nj < 8; nj++) {
                uint32_t bf[2];
                bf[0] = Vs[kk + tig][nj * 8 + gID];
                bf[1] = Vs[kk + tig + 4][nj * 8 + gID];
                mma_tf32(oacc[nj], af, bf);
            }
        }
    }

    // row-sum reduction (quad)
    l0 += __shfl_xor_sync(0xFFFFFFFFu, l0, 1);
    l0 += __shfl_xor_sync(0xFFFFFFFFu, l0, 2);
    l1 += __shfl_xor_sync(0xFFFFFFFFu, l1, 1);
    l1 += __shfl_xor_sync(0xFFFFFFFFu, l1, 2);
    const float inv0 = 1.f / l0;
    const float inv1 = 1.f / l1;

    // save 1/l for the overlapped normalize slice
    if (tig == 0) {
        linv[(size_t)bh * S + q0g] = inv0;
        linv[(size_t)bh * S + q1g] = inv1;
    }

    // write ctx = O_unnorm * inv
#pragma unroll
    for (int nj = 0; nj < 8; nj++) {
        const int col = h * DK + nj * 8 + 2 * tig;
        *(float2*)&ctx[(size_t)(b * S + q0g) * D + col] =
            make_float2(oacc[nj][0] * inv0, oacc[nj][1] * inv0);
        *(float2*)&ctx[(size_t)(b * S + q1g) * D + col] =
            make_float2(oacc[nj][2] * inv1, oacc[nj][3] * inv1);
    }
}

// ---------------------------------------------------------------------------
// Row LayerNorm
// ---------------------------------------------------------------------------
__global__ __launch_bounds__(256) void ln_kernel(
    const float* __restrict__ x, const float* __restrict__ gamma,
    const float* __restrict__ beta, float* __restrict__ y)
{
    const size_t row = blockIdx.x;
    const float* xr = x + row * (size_t)D;
    float* yr = y + row * (size_t)D;
    const int tid = threadIdx.x;

    __shared__ float rs[256], rs2[256];

    float s = 0.f, s2 = 0.f;
#pragma unroll
    for (int i = 0; i < 4; i++) {
        float v = xr[tid + i * 256];
        s += v;
        s2 += v * v;
    }
    rs[tid] = s; rs2[tid] = s2;
    __syncthreads();
#pragma unroll
    for (int k = 128; k > 0; k >>= 1) {
        if (tid < k) { rs[tid] += rs[tid + k]; rs2[tid] += rs2[tid + k]; }
        __syncthreads();
    }
    const float mean = rs[0] * (1.f / D);
    const float var  = rs2[0] * (1.f / D) - mean * mean;
    const float rstd = rsqrtf(var + 1e-5f);

#pragma unroll
    for (int i = 0; i < 4; i++) {
        int c = tid + i * 256;
        yr[c] = (xr[c] - mean) * rstd * gamma[c] + beta[c];
    }
}

// ---------------------------------------------------------------------------
// Launch
// ---------------------------------------------------------------------------
extern "C" void kernel_launch(void* const* d_in, const int* in_sizes, int n_in,
                              void* d_out, int out_size)
{
    const float* query = (const float*)d_in[0];
    const float* key   = (const float*)d_in[1];
    const float* value = (const float*)d_in[2];
    const float* wq = (const float*)d_in[4];
    const float* bq = (const float*)d_in[5];
    const float* wk = (const float*)d_in[6];
    const float* bk = (const float*)d_in[7];
    const float* wv = (const float*)d_in[8];
    const float* bv = (const float*)d_in[9];
    const float* wo = (const float*)d_in[10];
    const float* bo = (const float*)d_in[11];
    const float* gamma = (const float*)d_in[12];
    const float* beta  = (const float*)d_in[13];

    float* y = (float*)d_out;

    float *Qp, *Kp, *Vp, *ctxp, *xp, *attnp, *linvp;
    cudaGetSymbolAddress((void**)&Qp,    g_Q);
    cudaGetSymbolAddress((void**)&Kp,    g_K);
    cudaGetSymbolAddress((void**)&Vp,    g_V);
    cudaGetSymbolAddress((void**)&ctxp,  g_ctx);
    cudaGetSymbolAddress((void**)&xp,    g_x);
    cudaGetSymbolAddress((void**)&attnp, g_attn);
    cudaGetSymbolAddress((void**)&linvp, g_linv);

    const bool need_attn = ((size_t)out_size >= YSIZE + ATTNSIZE);
    float* attnout = need_attn ? (y + YSIZE) : attnp;

    cudaFuncSetAttribute(fused_attn,
                         cudaFuncAttributeMaxDynamicSharedMemorySize, FB_SMEM);

    // z=0..2: Q/K/V projections; z=3: attn upper-triangle zero-fill (overlapped)
    qkv_gemm<<<dim3(D / 128, M / 128, 4), 128>>>(
        query, key, value, wq, wk, wv, bq, bk, bv, Qp, Kp, Vp, attnout);

    fused_attn<<<dim3(S / 128, B * H), 256, FB_SMEM>>>(
        Qp, Kp, Vp, attnout, ctxp, linvp);

    // z=0: output projection; z=1: attn row normalization (overlapped)
    outproj_gemm<<<dim3(D / 128, M / 128, 2), 128>>>(
        ctxp, wo, bo, query, xp, attnout, linvp);

    ln_kernel<<<M, 256>>>(xp, gamma, beta, y);
}

// round 15
// speedup vs baseline: 1.3858x; 1.3858x over previous
#include <cuda_runtime.h>
#include <cstdint>
#include <math.h>

// Problem constants
static constexpr int B  = 8;
static constexpr int S  = 1024;
static constexpr int D  = 1024;
static constexpr int H  = 16;
static constexpr int DK = 64;
static constexpr int M  = B * S;

static constexpr size_t YSIZE    = (size_t)B * S * D;
static constexpr size_t ATTNSIZE = (size_t)B * H * S * S;

// Scratch
__device__ float g_Q[YSIZE];
__device__ float g_K[YSIZE];
__device__ float g_V[YSIZE];
__device__ float g_ctx[YSIZE];
__device__ float g_x[YSIZE];
__device__ float g_attn[ATTNSIZE];

__device__ __forceinline__ uint32_t f32_to_tf32_rn(float x) {
    uint32_t r;
    asm("cvt.rna.tf32.f32 %0, %1;" : "=r"(r) : "f"(x));
    return r;
}

__device__ __forceinline__ float ex2f(float x) {
    float r;
    asm("ex2.approx.f32 %0, %1;" : "=f"(r) : "f"(x));
    return r;
}

// streaming (evict-first) stores for write-once data
__device__ __forceinline__ void st_cs_f2(float* p, float a, float b) {
    asm volatile("st.global.cs.v2.f32 [%0], {%1, %2};" :: "l"(p), "f"(a), "f"(b) : "memory");
}
__device__ __forceinline__ void st_cs_f4(float* p, float4 v) {
    asm volatile("st.global.cs.v4.f32 [%0], {%1, %2, %3, %4};"
                 :: "l"(p), "f"(v.x), "f"(v.y), "f"(v.z), "f"(v.w) : "memory");
}

__device__ __forceinline__ void mma_tf32(float c[4], const uint32_t a[4], const uint32_t b[2]) {
    asm volatile(
        "mma.sync.aligned.m16n8k8.row.col.f32.tf32.tf32.f32 "
        "{%0,%1,%2,%3}, {%4,%5,%6,%7}, {%8,%9}, {%0,%1,%2,%3};"
        : "+f"(c[0]), "+f"(c[1]), "+f"(c[2]), "+f"(c[3])
        : "r"(a[0]), "r"(a[1]), "r"(a[2]), "r"(a[3]), "r"(b[0]), "r"(b[1]));
}

// ===========================================================================
// Dense GEMM body: tf32 warp MMA, warp tile 64x64, block 128x128, 4 warps,
// 2-stage double-buffered smem, register prefetch.
// ===========================================================================
static constexpr int BKg = 16;

__device__ __forceinline__ void gemm_body(
    const float* __restrict__ A, const float* __restrict__ W,
    const float* __restrict__ bias, const float* __restrict__ res,
    float* __restrict__ C, int Kk, int Nn, int bm, int bn)
{
    __shared__ uint32_t As[2][128][20];
    __shared__ uint32_t Ws[2][128][20];

    const int tid  = threadIdx.x;        // 0..127
    const int wid  = tid >> 5;           // 0..3
    const int lane = tid & 31;
    const int warp_m = wid >> 1;
    const int warp_n = wid & 1;
    const int gID = lane >> 2;
    const int tig = lane & 3;

    const int srow = tid >> 2;           // 0..31
    const int skc  = (tid & 3) * 4;

    const float* Ag[4];
    const float* Wg[4];
#pragma unroll
    for (int i = 0; i < 4; i++) {
        Ag[i] = A + (size_t)(bm + srow + i * 32) * Kk + skc;
        Wg[i] = W + (size_t)(bn + srow + i * 32) * Kk + skc;
    }

    float acc[4][8][4];
#pragma unroll
    for (int i = 0; i < 4; i++)
#pragma unroll
        for (int j = 0; j < 8; j++)
#pragma unroll
            for (int r = 0; r < 4; r++) acc[i][j][r] = 0.f;

    const int NCH = Kk / BKg;

    float4 ra[4], rw[4];
#pragma unroll
    for (int i = 0; i < 4; i++) {
        ra[i] = *(const float4*)Ag[i];
        rw[i] = *(const float4*)Wg[i];
    }

#pragma unroll
    for (int i = 0; i < 4; i++) {
        *(uint4*)&As[0][srow + i * 32][skc] = make_uint4(
            f32_to_tf32_rn(ra[i].x), f32_to_tf32_rn(ra[i].y),
            f32_to_tf32_rn(ra[i].z), f32_to_tf32_rn(ra[i].w));
        *(uint4*)&Ws[0][srow + i * 32][skc] = make_uint4(
            f32_to_tf32_rn(rw[i].x), f32_to_tf32_rn(rw[i].y),
            f32_to_tf32_rn(rw[i].z), f32_to_tf32_rn(rw[i].w));
    }
    __syncthreads();

    for (int c = 0; c < NCH; c++) {
        const int s = c & 1;
        const bool more = (c + 1 < NCH);

        if (more) {
#pragma unroll
            for (int i = 0; i < 4; i++) {
                Ag[i] += BKg; Wg[i] += BKg;
                ra[i] = *(const float4*)Ag[i];
                rw[i] = *(const float4*)Wg[i];
            }
        }

#pragma unroll
        for (int kk = 0; kk < BKg; kk += 8) {
            uint32_t af[4][4];
            uint32_t bf[8][2];
#pragma unroll
            for (int mi = 0; mi < 4; mi++) {
                const int mr = warp_m * 64 + mi * 16 + gID;
                af[mi][0] = As[s][mr][kk + tig];
                af[mi][1] = As[s][mr + 8][kk + tig];
                af[mi][2] = As[s][mr][kk + tig + 4];
                af[mi][3] = As[s][mr + 8][kk + tig + 4];
            }
#pragma unroll
            for (int nj = 0; nj < 8; nj++) {
                const int nr = warp_n * 64 + nj * 8 + gID;
                bf[nj][0] = Ws[s][nr][kk + tig];
                bf[nj][1] = Ws[s][nr][kk + tig + 4];
            }
#pragma unroll
            for (int mi = 0; mi < 4; mi++)
#pragma unroll
                for (int nj = 0; nj < 8; nj++)
                    mma_tf32(acc[mi][nj], af[mi], bf[nj]);
        }

        if (more) {
            const int t = s ^ 1;
#pragma unroll
            for (int i = 0; i < 4; i++) {
                *(uint4*)&As[t][srow + i * 32][skc] = make_uint4(
                    f32_to_tf32_rn(ra[i].x), f32_to_tf32_rn(ra[i].y),
                    f32_to_tf32_rn(ra[i].z), f32_to_tf32_rn(ra[i].w));
                *(uint4*)&Ws[t][srow + i * 32][skc] = make_uint4(
                    f32_to_tf32_rn(rw[i].x), f32_to_tf32_rn(rw[i].y),
                    f32_to_tf32_rn(rw[i].z), f32_to_tf32_rn(rw[i].w));
            }
        }
        __syncthreads();
    }

    const bool has_res = (res != nullptr);
#pragma unroll
    for (int mi = 0; mi < 4; mi++) {
        const int r0 = bm + warp_m * 64 + mi * 16 + gID;
#pragma unroll
        for (int nj = 0; nj < 8; nj++) {
            const int c0 = bn + warp_n * 64 + nj * 8 + tig * 2;
            const float b0 = bias[c0], b1 = bias[c0 + 1];
            float2 o0 = make_float2(acc[mi][nj][0] + b0, acc[mi][nj][1] + b1);
            float2 o1 = make_float2(acc[mi][nj][2] + b0, acc[mi][nj][3] + b1);
            const size_t i0 = (size_t)r0 * Nn + c0;
            const size_t i1 = (size_t)(r0 + 8) * Nn + c0;
            if (has_res) {
                float2 rv0 = *(const float2*)&res[i0];
                float2 rv1 = *(const float2*)&res[i1];
                o0.x += rv0.x; o0.y += rv0.y;
                o1.x += rv1.x; o1.y += rv1.y;
            }
            *(float2*)&C[i0] = o0;
            *(float2*)&C[i1] = o1;
        }
    }
}

// Merged QKV projection + attn upper-triangle zero-fill (overlapped).
// z = 0..2 : Q/K/V GEMM; z = 3 : zero-fill attn tiles (k-tile > q-tile).
__global__ void __launch_bounds__(128, 2) qkv_gemm(
    const float* __restrict__ q_in, const float* __restrict__ k_in,
    const float* __restrict__ v_in,
    const float* __restrict__ wq, const float* __restrict__ wk,
    const float* __restrict__ wv,
    const float* __restrict__ bq, const float* __restrict__ bk,
    const float* __restrict__ bv,
    float* __restrict__ Qo, float* __restrict__ Ko, float* __restrict__ Vo,
    float* __restrict__ attnout)
{
    if (blockIdx.z == 3) {
        // 3584 zero tiles (128x128) = 512 blocks * 7 tiles
        const int bid = blockIdx.y * 8 + blockIdx.x;          // 0..511
        for (int t = bid * 7; t < bid * 7 + 7; t++) {
            const int bh = t / 28;
            int r = t % 28;
            int qt = 0;
            while (r >= 7 - qt) { r -= 7 - qt; qt++; }
            const int kt = qt + 1 + r;
            float* tile = attnout + (size_t)bh * S * S
                        + (size_t)qt * 128 * S + (size_t)kt * 128;
            const float4 z4 = make_float4(0.f, 0.f, 0.f, 0.f);
            for (int i = threadIdx.x; i < 128 * 32; i += 128) {
                const int row = i >> 5, c4 = i & 31;
                st_cs_f4(&tile[(size_t)row * S + c4 * 4], z4);
            }
        }
        return;
    }
    const float* A; const float* W; const float* bias; float* C;
    if (blockIdx.z == 0)      { A = q_in; W = wq; bias = bq; C = Qo; }
    else if (blockIdx.z == 1) { A = k_in; W = wk; bias = bk; C = Ko; }
    else                      { A = v_in; W = wv; bias = bv; C = Vo; }
    gemm_body(A, W, bias, nullptr, C, D, D, blockIdx.y * 128, blockIdx.x * 128);
}

__global__ void __launch_bounds__(128, 2) gemm_tf32_mma(
    const float* __restrict__ A, const float* __restrict__ W,
    const float* __restrict__ bias, const float* __restrict__ res,
    float* __restrict__ C, int Kk, int Nn)
{
    gemm_body(A, W, bias, res, C, Kk, Nn, blockIdx.y * 128, blockIdx.x * 128);
}

// ===========================================================================
// Fused attention, two-pass (R12 structure); attn stores use st.global.cs.
// ===========================================================================
static constexpr int FB_QP = 68;
static constexpr int FB_KP = 68;
static constexpr int FB_VP = 72;
static constexpr int FB_PP = 68;
static constexpr int FB_OFF_K = 128 * FB_QP;
static constexpr int FB_OFF_V = FB_OFF_K + 64 * FB_KP;
static constexpr int FB_OFF_P = FB_OFF_V + 64 * FB_VP;
static constexpr int FB_SMEM  = (FB_OFF_P + 128 * FB_PP) * 4;   // 105472

__global__ void __launch_bounds__(256, 2) fused_attn(
    const float* __restrict__ Qg, const float* __restrict__ Kg,
    const float* __restrict__ Vg, float* __restrict__ attn,
    float* __restrict__ ctx)
{
    extern __shared__ uint32_t sm[];
    uint32_t (*Qs)[FB_QP] = (uint32_t(*)[FB_QP])sm;
    uint32_t (*Ks)[FB_KP] = (uint32_t(*)[FB_KP])(sm + FB_OFF_K);
    uint32_t (*Vs)[FB_VP] = (uint32_t(*)[FB_VP])(sm + FB_OFF_V);
    uint32_t (*Ps)[FB_PP] = (uint32_t(*)[FB_PP])(sm + FB_OFF_P);

    const int NQT = S / 128;
    const int qt = NQT - 1 - blockIdx.x;
    const int bh = blockIdx.y;
    const int b = bh >> 4, h = bh & 15;
    const int q0 = qt * 128;

    const float* Qbase = Qg + (size_t)b * S * D + h * DK;
    const float* Kbase = Kg + (size_t)b * S * D + h * DK;
    const float* Vbase = Vg + (size_t)b * S * D + h * DK;
    float* arow = attn + (size_t)bh * S * S;

    const int tid  = threadIdx.x;
    const int wid  = tid >> 5;
    const int lane = tid & 31;
    const int gID  = lane >> 2;
    const int tig  = lane & 3;
    const int w16  = wid * 16;
    const int r0l  = w16 + gID;
    const int r1l  = r0l + 8;
    const int q0g  = q0 + r0l;
    const int q1g  = q0 + r1l;

    const int str = tid >> 4;
    const int stc = (tid & 15) * 4;

#pragma unroll
    for (int i = 0; i < 8; i++) {
        const int f = tid + i * 256;
        const int r = f >> 4, c4 = f & 15;
        float4 v = *(const float4*)&Qbase[(size_t)(q0 + r) * D + c4 * 4];
        *(uint4*)&Qs[r][c4 * 4] = make_uint4(
            f32_to_tf32_rn(v.x), f32_to_tf32_rn(v.y),
            f32_to_tf32_rn(v.z), f32_to_tf32_rn(v.w));
    }

    const float C2 = 0.18033688011112042f;   // 0.125 * log2(e)
    const int NKT = (qt + 1) * 2;
    float l0 = 0.f, l1 = 0.f;

    float4 pk[4];
#pragma unroll
    for (int i = 0; i < 4; i++)
        pk[i] = *(const float4*)&Kbase[(size_t)(str + i * 16) * D + stc];

    // ---------------- Pass A ----------------
    for (int kt = 0; kt < NKT; kt++) {
        const int k0 = kt * 64;
        const bool tail = (k0 + 63 > q0);

#pragma unroll
        for (int i = 0; i < 4; i++) {
            *(uint4*)&Ks[str + i * 16][stc] = make_uint4(
                f32_to_tf32_rn(pk[i].x), f32_to_tf32_rn(pk[i].y),
                f32_to_tf32_rn(pk[i].z), f32_to_tf32_rn(pk[i].w));
        }
        __syncthreads();

        if (kt + 1 < NKT) {
            const int kn = k0 + 64;
#pragma unroll
            for (int i = 0; i < 4; i++)
                pk[i] = *(const float4*)&Kbase[(size_t)(kn + str + i * 16) * D + stc];
        }

        float sacc[8][4];
#pragma unroll
        for (int j = 0; j < 8; j++)
#pragma unroll
            for (int r = 0; r < 4; r++) sacc[j][r] = 0.f;

#pragma unroll
        for (int kk = 0; kk < 64; kk += 8) {
            uint32_t af[4];
            af[0] = Qs[r0l][kk + tig];
            af[1] = Qs[r1l][kk + tig];
            af[2] = Qs[r0l][kk + tig + 4];
            af[3] = Qs[r1l][kk + tig + 4];
#pragma unroll
            for (int nj = 0; nj < 8; nj++) {
                uint32_t bf[2];
                const int nr = nj * 8 + gID;
                bf[0] = Ks[nr][kk + tig];
                bf[1] = Ks[nr][kk + tig + 4];
                mma_tf32(sacc[nj], af, bf);
            }
        }

        if (tail) {
#pragma unroll
            for (int nj = 0; nj < 8; nj++) {
                const int c0 = k0 + nj * 8 + 2 * tig, c1 = c0 + 1;
                l0 += (c0 <= q0g) ? ex2f(sacc[nj][0] * C2) : 0.f;
                l0 += (c1 <= q0g) ? ex2f(sacc[nj][1] * C2) : 0.f;
                l1 += (c0 <= q1g) ? ex2f(sacc[nj][2] * C2) : 0.f;
                l1 += (c1 <= q1g) ? ex2f(sacc[nj][3] * C2) : 0.f;
            }
        } else {
#pragma unroll
            for (int nj = 0; nj < 8; nj++) {
                l0 += ex2f(sacc[nj][0] * C2) + ex2f(sacc[nj][1] * C2);
                l1 += ex2f(sacc[nj][2] * C2) + ex2f(sacc[nj][3] * C2);
            }
        }
        __syncthreads();
    }

    l0 += __shfl_xor_sync(0xFFFFFFFFu, l0, 1);
    l0 += __shfl_xor_sync(0xFFFFFFFFu, l0, 2);
    l1 += __shfl_xor_sync(0xFFFFFFFFu, l1, 1);
    l1 += __shfl_xor_sync(0xFFFFFFFFu, l1, 2);
    const float inv0 = 1.f / l0;
    const float inv1 = 1.f / l1;

    // ---------------- Pass B ----------------
    float oacc[8][4];
#pragma unroll
    for (int j = 0; j < 8; j++)
#pragma unroll
        for (int r = 0; r < 4; r++) oacc[j][r] = 0.f;

    float4 pv[4];
#pragma unroll
    for (int i = 0; i < 4; i++) {
        pk[i] = *(const float4*)&Kbase[(size_t)(str + i * 16) * D + stc];
        pv[i] = *(const float4*)&Vbase[(size_t)(str + i * 16) * D + stc];
    }

    for (int kt = 0; kt < NKT; kt++) {
        const int k0 = kt * 64;
        const bool tail = (k0 + 63 > q0);

        if (kt > 0) __syncthreads();
#pragma unroll
        for (int i = 0; i < 4; i++) {
            *(uint4*)&Ks[str + i * 16][stc] = make_uint4(
                f32_to_tf32_rn(pk[i].x), f32_to_tf32_rn(pk[i].y),
                f32_to_tf32_rn(pk[i].z), f32_to_tf32_rn(pk[i].w));
            *(uint4*)&Vs[str + i * 16][stc] = make_uint4(
                f32_to_tf32_rn(pv[i].x), f32_to_tf32_rn(pv[i].y),
                f32_to_tf32_rn(pv[i].z), f32_to_tf32_rn(pv[i].w));
        }
        __syncthreads();

        if (kt + 1 < NKT) {
            const int kn = k0 + 64;
#pragma unroll
            for (int i = 0; i < 4; i++) {
                pk[i] = *(const float4*)&Kbase[(size_t)(kn + str + i * 16) * D + stc];
                pv[i] = *(const float4*)&Vbase[(size_t)(kn + str + i * 16) * D + stc];
            }
        }

        float sacc[8][4];
#pragma unroll
        for (int j = 0; j < 8; j++)
#pragma unroll
            for (int r = 0; r < 4; r++) sacc[j][r] = 0.f;

#pragma unroll
        for (int kk = 0; kk < 64; kk += 8) {
            uint32_t af[4];
            af[0] = Qs[r0l][kk + tig];
            af[1] = Qs[r1l][kk + tig];
            af[2] = Qs[r0l][kk + tig + 4];
            af[3] = Qs[r1l][kk + tig + 4];
#pragma unroll
            for (int nj = 0; nj < 8; nj++) {
                uint32_t bf[2];
                const int nr = nj * 8 + gID;
                bf[0] = Ks[nr][kk + tig];
                bf[1] = Ks[nr][kk + tig + 4];
                mma_tf32(sacc[nj], af, bf);
            }
        }

#pragma unroll
        for (int nj = 0; nj < 8; nj++) {
            const int c0 = k0 + nj * 8 + 2 * tig, c1 = c0 + 1;
            float p00, p01, p10, p11;
            if (tail) {
                p00 = (c0 <= q0g) ? ex2f(sacc[nj][0] * C2) * inv0 : 0.f;
                p01 = (c1 <= q0g) ? ex2f(sacc[nj][1] * C2) * inv0 : 0.f;
                p10 = (c0 <= q1g) ? ex2f(sacc[nj][2] * C2) * inv1 : 0.f;
                p11 = (c1 <= q1g) ? ex2f(sacc[nj][3] * C2) * inv1 : 0.f;
            } else {
                p00 = ex2f(sacc[nj][0] * C2) * inv0;
                p01 = ex2f(sacc[nj][1] * C2) * inv0;
                p10 = ex2f(sacc[nj][2] * C2) * inv1;
                p11 = ex2f(sacc[nj][3] * C2) * inv1;
            }
            st_cs_f2(&arow[(size_t)q0g * S + c0], p00, p01);
            st_cs_f2(&arow[(size_t)q1g * S + c0], p10, p11);
            *(uint2*)&Ps[r0l][nj * 8 + 2 * tig] =
                make_uint2(f32_to_tf32_rn(p00), f32_to_tf32_rn(p01));
            *(uint2*)&Ps[r1l][nj * 8 + 2 * tig] =
                make_uint2(f32_to_tf32_rn(p10), f32_to_tf32_rn(p11));
        }
        __syncwarp();

#pragma unroll
        for (int kk = 0; kk < 64; kk += 8) {
            uint32_t af[4];
            af[0] = Ps[r0l][kk + tig];
            af[1] = Ps[r1l][kk + tig];
            af[2] = Ps[r0l][kk + tig + 4];
            af[3] = Ps[r1l][kk + tig + 4];
#pragma unroll
            for (int nj = 0; nj < 8; nj++) {
                uint32_t bf[2];
                bf[0] = Vs[kk + tig][nj * 8 + gID];
                bf[1] = Vs[kk + tig + 4][nj * 8 + gID];
                mma_tf32(oacc[nj], af, bf);
            }
        }
    }

    // write ctx (already normalized)
#pragma unroll
    for (int nj = 0; nj < 8; nj++) {
        const int col = h * DK + nj * 8 + 2 * tig;
        *(float2*)&ctx[(size_t)(b * S + q0g) * D + col] =
            make_float2(oacc[nj][0], oacc[nj][1]);
        *(float2*)&ctx[(size_t)(b * S + q1g) * D + col] =
            make_float2(oacc[nj][2], oacc[nj][3]);
    }
}

// ---------------------------------------------------------------------------
// Row LayerNorm
// ---------------------------------------------------------------------------
__global__ __launch_bounds__(256) void ln_kernel(
    const float* __restrict__ x, const float* __restrict__ gamma,
    const float* __restrict__ beta, float* __restrict__ y)
{
    const size_t row = blockIdx.x;
    const float* xr = x + row * (size_t)D;
    float* yr = y + row * (size_t)D;
    const int tid = threadIdx.x;

    __shared__ float rs[256], rs2[256];

    float s = 0.f, s2 = 0.f;
#pragma unroll
    for (int i = 0; i < 4; i++) {
        float v = xr[tid + i * 256];
        s += v;
        s2 += v * v;
    }
    rs[tid] = s; rs2[tid] = s2;
    __syncthreads();
#pragma unroll
    for (int k = 128; k > 0; k >>= 1) {
        if (tid < k) { rs[tid] += rs[tid + k]; rs2[tid] += rs2[tid + k]; }
        __syncthreads();
    }
    const float mean = rs[0] * (1.f / D);
    const float var  = rs2[0] * (1.f / D) - mean * mean;
    const float rstd = rsqrtf(var + 1e-5f);

#pragma unroll
    for (int i = 0; i < 4; i++) {
        int c = tid + i * 256;
        yr[c] = (xr[c] - mean) * rstd * gamma[c] + beta[c];
    }
}

// ---------------------------------------------------------------------------
// Launch
// ---------------------------------------------------------------------------
extern "C" void kernel_launch(void* const* d_in, const int* in_sizes, int n_in,
                              void* d_out, int out_size)
{
    const float* query = (const float*)d_in[0];
    const float* key   = (const float*)d_in[1];
    const float* value = (const float*)d_in[2];
    const float* wq = (const float*)d_in[4];
    const float* bq = (const float*)d_in[5];
    const float* wk = (const float*)d_in[6];
    const float* bk = (const float*)d_in[7];
    const float* wv = (const float*)d_in[8];
    const float* bv = (const float*)d_in[9];
    const float* wo = (const float*)d_in[10];
    const float* bo = (const float*)d_in[11];
    const float* gamma = (const float*)d_in[12];
    const float* beta  = (const float*)d_in[13];

    float* y = (float*)d_out;

    float *Qp, *Kp, *Vp, *ctxp, *xp, *attnp;
    cudaGetSymbolAddress((void**)&Qp,   g_Q);
    cudaGetSymbolAddress((void**)&Kp,   g_K);
    cudaGetSymbolAddress((void**)&Vp,   g_V);
    cudaGetSymbolAddress((void**)&ctxp, g_ctx);
    cudaGetSymbolAddress((void**)&xp,   g_x);
    cudaGetSymbolAddress((void**)&attnp, g_attn);

    const bool need_attn = ((size_t)out_size >= YSIZE + ATTNSIZE);
    float* attnout = need_attn ? (y + YSIZE) : attnp;

    cudaFuncSetAttribute(fused_attn,
                         cudaFuncAttributeMaxDynamicSharedMemorySize, FB_SMEM);

    // z=0..2: Q/K/V projections; z=3: attn upper-triangle zero-fill (overlapped)
    qkv_gemm<<<dim3(D / 128, M / 128, 4), 128>>>(
        query, key, value, wq, wk, wv, bq, bk, bv, Qp, Kp, Vp, attnout);

    fused_attn<<<dim3(S / 128, B * H), 256, FB_SMEM>>>(Qp, Kp, Vp, attnout, ctxp);

    gemm_tf32_mma<<<dim3(D / 128, M / 128), 128>>>(ctxp, wo, bo, query, xp, D, D);
    ln_kernel<<<M, 256>>>(xp, gamma, beta, y);
}